// round 5
// baseline (speedup 1.0000x reference)
#include <cuda_runtime.h>
#include <cstdint>
#include <math.h>

#define HH 128
#define WW 128
#define HW (HH*WW)
#define CB 64
#define BB 16
#define NCO 80          // fused N: 64 main co + 16 SE co

// ---------------- scratch (no cudaMalloc allowed) ----------------
__device__ float g_y[BB*576];                  // channel attention [b][ci*9+k]
__device__ float g_wall[BB*9*CB*NCO];          // fused weights [b][k][ci][80], tf32-rounded
__device__ float g_hidden[BB*16*HW];           // SE conv1 output
__device__ float g_A[BB*HW];                   // spatial attention
__device__ float g_mean[BB*CB];                // pooled means
__device__ float g_xc[(size_t)BB*CB*HW];       // tf32-rounded copy of x (64MB)

__device__ __forceinline__ float to_tf32(float x) {
    float r; asm("cvt.rna.tf32.f32 %0, %1;" : "=f"(r) : "f"(x)); return r;
}
__device__ __forceinline__ void mma8(float* d, const uint32_t* a, const uint32_t* b) {
    asm volatile(
        "mma.sync.aligned.m16n8k8.row.col.f32.tf32.tf32.f32 "
        "{%0,%1,%2,%3}, {%4,%5,%6,%7}, {%8,%9}, {%0,%1,%2,%3};\n"
        : "+f"(d[0]), "+f"(d[1]), "+f"(d[2]), "+f"(d[3])
        : "r"(a[0]), "r"(a[1]), "r"(a[2]), "r"(a[3]), "r"(b[0]), "r"(b[1]));
}
__device__ __forceinline__ void cp4z(uint32_t dst, const void* src, bool pred) {
    asm volatile("cp.async.ca.shared.global [%0], [%1], 4, %2;"
                 :: "r"(dst), "l"(src), "r"(pred ? 4u : 0u));
}
__device__ __forceinline__ void cp16(uint32_t dst, const void* src) {
    asm volatile("cp.async.cg.shared.global [%0], [%1], 16;" :: "r"(dst), "l"(src));
}
#define CP_COMMIT() asm volatile("cp.async.commit_group;" ::: "memory")

__device__ __forceinline__ uint32_t smem_u32(const void* p) {
    uint32_t a;
    asm("{ .reg .u64 t; cvta.to.shared.u64 t, %1; cvt.u32.u64 %0, t; }" : "=r"(a) : "l"(p));
    return a;
}

// ---------------- stage 1: tf32 pre-round + global average pool ----------------
__global__ void __launch_bounds__(256) convert_pool(const float* __restrict__ x) {
    int c = blockIdx.x, b = blockIdx.y, t = threadIdx.x;
    const float4* p = (const float4*)(x + ((size_t)(b * CB + c)) * HW);
    float4* o = (float4*)(g_xc + ((size_t)(b * CB + c)) * HW);
    float sum = 0.f;
    #pragma unroll 4
    for (int i = t; i < HW / 4; i += 256) {
        float4 v = p[i];
        sum += (v.x + v.y) + (v.z + v.w);
        v.x = to_tf32(v.x); v.y = to_tf32(v.y); v.z = to_tf32(v.z); v.w = to_tf32(v.w);
        o[i] = v;
    }
    #pragma unroll
    for (int off = 16; off; off >>= 1) sum += __shfl_xor_sync(0xffffffffu, sum, off);
    __shared__ float ws[8];
    if ((t & 31) == 0) ws[t >> 5] = sum;
    __syncthreads();
    if (t == 0) {
        float s = 0.f;
        #pragma unroll
        for (int i = 0; i < 8; i++) s += ws[i];
        g_mean[b * CB + c] = s * (1.f / (float)HW);
    }
}

// ---------------- stage 2: FC chain -> y ----------------
__global__ void attn_fc(const float* __restrict__ fc_w1, const float* __restrict__ fc_w2) {
    int b = blockIdx.x, t = threadIdx.x;
    __shared__ float smean[64];
    __shared__ float sh[4];
    if (t < 64) smean[t] = g_mean[b * 64 + t];
    __syncthreads();
    if (t < 4) {
        float s = 0.f;
        #pragma unroll
        for (int c = 0; c < 64; c++) s += smean[c] * fc_w1[t * 64 + c];
        sh[t] = fmaxf(s, 0.f);
    }
    __syncthreads();
    for (int j = t; j < 576; j += blockDim.x) {
        float s = 0.f;
        #pragma unroll
        for (int r = 0; r < 4; r++) s += sh[r] * fc_w2[j * 4 + r];
        g_y[b * 576 + j] = 1.f / (1.f + expf(-s));
    }
}

// ---------------- stage 3: fused weights [b][k][ci][80], tf32 ----------------
__global__ void build_wall(const float* __restrict__ weight,
                           const float* __restrict__ se_w1) {
    int idx = blockIdx.x * blockDim.x + threadIdx.x;
    if (idx >= BB * 9 * CB * NCO) return;
    int co = idx % NCO;
    int ci = (idx / NCO) & 63;
    int k  = (idx / (NCO * 64)) % 9;
    int b  = idx / (NCO * 64 * 9);
    float v;
    if (co < 64) v = weight[(co * 64 + ci) * 9 + k] * g_y[b * 576 + ci * 9 + k];
    else         v = se_w1[((co - 64) * 64 + ci) * 9 + k];
    g_wall[idx] = to_tf32(v);
}

// ---------------- fused tf32 mma conv: N=80 (64 main raw -> out, 16 SE relu -> hidden) ----
// CTA: batch b (blockIdx.y), 4 image rows R0..R0+3, 512 thr = 16 warps.
// Warp w: row prow = w>>2, 32-col band (w&3)*32; warp tile M=32 (2 m16), N=80 (10 n8).
// K = 9 taps x 64 ci as 4 chunks of 16 ci; taps = shifted smem reads.
// smem/buffer: sx[ci16][row6][col132] stride 792, sw[(k*16+ci)][88] (banks 24*tig+g, CF).
#define SX_WORDS (16*6*132)
#define SW_WORDS (9*16*88)
#define BUF_WORDS (SX_WORDS + SW_WORDS)
#define DYN_SMEM (2 * BUF_WORDS * 4)

__global__ void __launch_bounds__(512, 1) conv_fused(float* __restrict__ outp) {
    extern __shared__ uint32_t sm[];
    const uint32_t smb = smem_u32(sm);
    const int tid = threadIdx.x, wid = tid >> 5, lane = tid & 31;
    const int g = lane >> 2, tig = lane & 3;
    const int b = blockIdx.y, R0 = blockIdx.x * 4;
    const int prow = wid >> 2, colbase = (wid & 3) * 32;

    // hoisted x-staging geometry: thread -> (ci_x, r_x, col quarter)
    const int sr = tid >> 2, q = tid & 3;
    const int ci_x = sr / 6, r_x = sr - ci_x * 6;
    const int gy = R0 - 1 + r_x;
    const bool xactive = sr < 96;
    const bool rowok = xactive && ((unsigned)gy < (unsigned)HH);
    const float* xrowb = g_xc + ((size_t)b * 64) * HW + (size_t)gy * WW - 1;
    const int c0 = q * 33;
    const uint32_t dxrow_off = (uint32_t)(ci_x * 792 + r_x * 132) * 4;

    auto stage = [&](int cc, int bufi) {
        const int ci0 = cc * 16;
        const uint32_t bufb = smb + (uint32_t)bufi * (BUF_WORDS * 4);
        if (xactive) {
            const float* srcrow = xrowb + (size_t)(ci0 + ci_x) * HW;
            const uint32_t drow = bufb + dxrow_off;
            #pragma unroll
            for (int j = 0; j < 33; j++) {
                int c = c0 + j;
                bool ok = rowok && ((unsigned)(c - 1) < (unsigned)WW);
                cp4z(drow + c * 4, srcrow + c, ok);
            }
        }
        // weights: 9*16*80/4 = 2880 16B-quads
        #pragma unroll
        for (int it = 0; it < 6; it++) {
            int idx = tid + it * 512;
            if (idx < 2880) {
                int co4 = idx % 20;
                int rem = idx / 20;
                int ci = rem & 15, k = rem >> 4;
                const float* src = g_wall +
                    (((size_t)b * 9 + k) * 64 + ci0 + ci) * NCO + co4 * 4;
                uint32_t dst = bufb +
                    (uint32_t)(SX_WORDS + (k * 16 + ci) * 88 + co4 * 4) * 4;
                cp16(dst, src);
            }
        }
    };

    float d[2][10][4];
    #pragma unroll
    for (int mt = 0; mt < 2; mt++)
        #pragma unroll
        for (int nt = 0; nt < 10; nt++)
            #pragma unroll
            for (int r = 0; r < 4; r++) d[mt][nt][r] = 0.f;

    stage(0, 0);
    CP_COMMIT();

    for (int cc = 0; cc < 4; ++cc) {
        if (cc < 3) {
            stage(cc + 1, (cc + 1) & 1);
            CP_COMMIT();
            asm volatile("cp.async.wait_group 1;" ::: "memory");
        } else {
            asm volatile("cp.async.wait_group 0;" ::: "memory");
        }
        __syncthreads();

        const uint32_t* sxp = sm + (cc & 1) * BUF_WORDS;
        const uint32_t* swp = sxp + SX_WORDS;

        #pragma unroll
        for (int k = 0; k < 9; ++k) {
            const int dy = k / 3, dx = k % 3;
            #pragma unroll
            for (int s = 0; s < 2; ++s) {
                uint32_t af[2][4];
                #pragma unroll
                for (int mt = 0; mt < 2; ++mt) {
                    const int colb = colbase + mt * 16 + g + dx;
                    const int base0 = (s * 8 + tig) * 792 + (prow + dy) * 132 + colb;
                    const int base1 = (s * 8 + tig + 4) * 792 + (prow + dy) * 132 + colb;
                    af[mt][0] = sxp[base0];
                    af[mt][1] = sxp[base0 + 8];
                    af[mt][2] = sxp[base1];
                    af[mt][3] = sxp[base1 + 8];
                }
                const uint32_t* swk0 = swp + (k * 16 + s * 8 + tig) * 88 + g;
                const uint32_t* swk1 = swk0 + 4 * 88;
                #pragma unroll
                for (int nt = 0; nt < 10; ++nt) {
                    uint32_t bf[2];
                    bf[0] = swk0[nt * 8];
                    bf[1] = swk1[nt * 8];
                    mma8(d[0][nt], af[0], bf);
                    mma8(d[1][nt], af[1], bf);
                }
            }
        }
        __syncthreads();
    }

    // epilogue: nt 0..7 -> raw main output; nt 8..9 -> relu -> g_hidden
    const int grow = R0 + prow;
    #pragma unroll
    for (int mt = 0; mt < 2; ++mt) {
        const int col = colbase + mt * 16 + g;
        #pragma unroll
        for (int nt = 0; nt < 10; ++nt) {
            if (nt < 8) {
                const int co = nt * 8 + tig * 2;
                float* o0 = outp + ((size_t)(b * 64 + co)) * HW + grow * WW + col;
                float* o1 = o0 + HW;
                o0[0] = d[mt][nt][0];
                o1[0] = d[mt][nt][1];
                o0[8] = d[mt][nt][2];
                o1[8] = d[mt][nt][3];
            } else {
                const int co = (nt - 8) * 8 + tig * 2;
                float* o0 = g_hidden + ((size_t)(b * 16 + co)) * HW + grow * WW + col;
                float* o1 = o0 + HW;
                o0[0] = fmaxf(d[mt][nt][0], 0.f);
                o1[0] = fmaxf(d[mt][nt][1], 0.f);
                o0[8] = fmaxf(d[mt][nt][2], 0.f);
                o1[8] = fmaxf(d[mt][nt][3], 0.f);
            }
        }
    }
}

// ---------------- SE conv2 (16 -> 1, sigmoid) -> g_A ----------------
__global__ void __launch_bounds__(256) se_conv2(const float* __restrict__ se_w2) {
    __shared__ float sx[16][18][20];
    __shared__ float sw[144];
    int b = blockIdx.z;
    int x0 = blockIdx.x * 16, y0 = blockIdx.y * 16;
    int t = threadIdx.x;
    if (t < 144) sw[t] = se_w2[t];
    for (int idx = t; idx < 16 * 18 * 18; idx += 256) {
        int ci = idx / 324; int rem = idx - ci * 324;
        int r = rem / 18, cx = rem - r * 18;
        int gy = y0 + r - 1, gx = x0 + cx - 1;
        float v = 0.f;
        if ((unsigned)gy < HH && (unsigned)gx < WW)
            v = g_hidden[(b * 16 + ci) * HW + gy * WW + gx];
        sx[ci][r][cx] = v;
    }
    __syncthreads();
    int py = t >> 4, px = t & 15;
    float s = 0.f;
    #pragma unroll
    for (int ci = 0; ci < 16; ci++)
    #pragma unroll
    for (int k = 0; k < 9; k++)
        s += sw[ci * 9 + k] * sx[ci][py + k / 3][px + k % 3];
    g_A[b * HW + (y0 + py) * WW + x0 + px] = 1.f / (1.f + expf(-s));
}

// ---------------- final: out *= A ----------------
__global__ void __launch_bounds__(256) apply_A(float* __restrict__ outp) {
    int idx = blockIdx.x * 256 + threadIdx.x;       // over BB * HW/4
    int b = idx >> 12, p4 = idx & 4095;
    float4 a = ((const float4*)(g_A + b * HW))[p4];
    float4* o = (float4*)(outp + ((size_t)b * 64) * HW) + p4;
    #pragma unroll 8
    for (int c = 0; c < 64; c++) {
        float4 v = o[(size_t)c * (HW / 4)];
        v.x *= a.x; v.y *= a.y; v.z *= a.z; v.w *= a.w;
        o[(size_t)c * (HW / 4)] = v;
    }
}

extern "C" void kernel_launch(void* const* d_in, const int* in_sizes, int n_in,
                              void* d_out, int out_size) {
    const float* x      = (const float*)d_in[0];
    const float* weight = (const float*)d_in[1];
    const float* se_w1  = (const float*)d_in[2];
    const float* se_w2  = (const float*)d_in[3];
    const float* fc_w1  = (const float*)d_in[4];
    const float* fc_w2  = (const float*)d_in[5];
    float* out = (float*)d_out;

    cudaFuncSetAttribute(conv_fused, cudaFuncAttributeMaxDynamicSharedMemorySize, DYN_SMEM);

    convert_pool<<<dim3(CB, BB), 256>>>(x);                          // g_xc + g_mean
    attn_fc<<<BB, 576>>>(fc_w1, fc_w2);                              // g_y
    build_wall<<<(BB * 9 * CB * NCO + 255) / 256, 256>>>(weight, se_w1);
    conv_fused<<<dim3(32, BB), 512, DYN_SMEM>>>(out);                // raw out + g_hidden
    se_conv2<<<dim3(8, 8, BB), 256>>>(se_w2);                        // g_A
    apply_A<<<BB * HW / 4 / 256, 256>>>(out);                        // out *= A
}

// round 6
// speedup vs baseline: 1.2594x; 1.2594x over previous
#include <cuda_runtime.h>
#include <cstdint>
#include <math.h>

#define HH 128
#define WW 128
#define HW (HH*WW)
#define CB 64
#define BB 16

// ---------------- scratch (no cudaMalloc allowed) ----------------
__device__ float g_y[BB*576];                  // channel attention [b][ci*9+k]
__device__ float g_wm[BB*4*9*2*64*8];          // main weights [b][cc][k][s][co64][tig4][h2]
__device__ float g_ws[4*9*2*16*8];             // SE weights   [cc][k][s][co16][tig4][h2]
__device__ float g_hidden[BB*16*HW];           // SE conv1 output
__device__ float g_A[BB*HW];                   // spatial attention
__device__ float g_mean[BB*CB];                // pooled means
__device__ float g_xc[(size_t)BB*CB*HW];       // tf32-rounded copy of x (64MB)

__device__ __forceinline__ float to_tf32(float x) {
    float r; asm("cvt.rna.tf32.f32 %0, %1;" : "=f"(r) : "f"(x)); return r;
}
__device__ __forceinline__ void mma8(float* d, const uint32_t* a, const uint32_t* b) {
    asm volatile(
        "mma.sync.aligned.m16n8k8.row.col.f32.tf32.tf32.f32 "
        "{%0,%1,%2,%3}, {%4,%5,%6,%7}, {%8,%9}, {%0,%1,%2,%3};\n"
        : "+f"(d[0]), "+f"(d[1]), "+f"(d[2]), "+f"(d[3])
        : "r"(a[0]), "r"(a[1]), "r"(a[2]), "r"(a[3]), "r"(b[0]), "r"(b[1]));
}
__device__ __forceinline__ void cp4z(uint32_t dst, const void* src, bool pred) {
    asm volatile("cp.async.ca.shared.global [%0], [%1], 4, %2;"
                 :: "r"(dst), "l"(src), "r"(pred ? 4u : 0u));
}
__device__ __forceinline__ void cp16(uint32_t dst, const void* src) {
    asm volatile("cp.async.cg.shared.global [%0], [%1], 16;" :: "r"(dst), "l"(src));
}
#define CP_COMMIT() asm volatile("cp.async.commit_group;" ::: "memory")

__device__ __forceinline__ uint32_t smem_u32(const void* p) {
    uint32_t a;
    asm("{ .reg .u64 t; cvta.to.shared.u64 t, %1; cvt.u32.u64 %0, t; }" : "=r"(a) : "l"(p));
    return a;
}

// ---------------- stage 1: tf32 pre-round + global average pool ----------------
__global__ void __launch_bounds__(256) convert_pool(const float* __restrict__ x) {
    int c = blockIdx.x, b = blockIdx.y, t = threadIdx.x;
    const float4* p = (const float4*)(x + ((size_t)(b * CB + c)) * HW);
    float4* o = (float4*)(g_xc + ((size_t)(b * CB + c)) * HW);
    float sum = 0.f;
    #pragma unroll 4
    for (int i = t; i < HW / 4; i += 256) {
        float4 v = p[i];
        sum += (v.x + v.y) + (v.z + v.w);
        v.x = to_tf32(v.x); v.y = to_tf32(v.y); v.z = to_tf32(v.z); v.w = to_tf32(v.w);
        o[i] = v;
    }
    #pragma unroll
    for (int off = 16; off; off >>= 1) sum += __shfl_xor_sync(0xffffffffu, sum, off);
    __shared__ float ws[8];
    if ((t & 31) == 0) ws[t >> 5] = sum;
    __syncthreads();
    if (t == 0) {
        float s = 0.f;
        #pragma unroll
        for (int i = 0; i < 8; i++) s += ws[i];
        g_mean[b * CB + c] = s * (1.f / (float)HW);
    }
}

// ---------------- stage 2: FC chain -> y ----------------
__global__ void attn_fc(const float* __restrict__ fc_w1, const float* __restrict__ fc_w2) {
    int b = blockIdx.x, t = threadIdx.x;
    __shared__ float smean[64];
    __shared__ float sh[4];
    if (t < 64) smean[t] = g_mean[b * 64 + t];
    __syncthreads();
    if (t < 4) {
        float s = 0.f;
        #pragma unroll
        for (int c = 0; c < 64; c++) s += smean[c] * fc_w1[t * 64 + c];
        sh[t] = fmaxf(s, 0.f);
    }
    __syncthreads();
    for (int j = t; j < 576; j += blockDim.x) {
        float s = 0.f;
        #pragma unroll
        for (int r = 0; r < 4; r++) s += sh[r] * fc_w2[j * 4 + r];
        g_y[b * 576 + j] = 1.f / (1.f + expf(-s));
    }
}

// ---------------- stage 3: pre-swizzled weights, mma B-fragment layout ----------------
// layout: [.. block(b,cc) ..][k][s][co][tig][h], ci = cc*16 + s*8 + tig + 4*h
#define WM_TOTAL (BB*4*9*2*64*8)
#define WS_TOTAL (4*9*2*16*8)
__global__ void build_w(const float* __restrict__ weight, const float* __restrict__ se_w1) {
    int idx = blockIdx.x * blockDim.x + threadIdx.x;
    if (idx < WM_TOTAL) {
        int h   = idx & 1;
        int tig = (idx >> 1) & 3;
        int co  = (idx >> 3) & 63;
        int s   = (idx >> 9) & 1;
        int k   = (idx >> 10) % 9;
        int rem = idx / (9 << 10);
        int cc  = rem & 3, b = rem >> 2;
        int ci  = cc * 16 + s * 8 + tig + 4 * h;
        g_wm[idx] = to_tf32(weight[(co * 64 + ci) * 9 + k] * g_y[b * 576 + ci * 9 + k]);
    } else {
        int j = idx - WM_TOTAL;
        if (j >= WS_TOTAL) return;
        int h   = j & 1;
        int tig = (j >> 1) & 3;
        int co  = (j >> 3) & 15;
        int s   = (j >> 7) & 1;
        int k   = (j >> 8) % 9;
        int cc  = j / (9 << 8);
        int ci  = cc * 16 + s * 8 + tig + 4 * h;
        g_ws[j] = to_tf32(se_w1[(co * 64 + ci) * 9 + k]);
    }
}

// ---------------- tf32 mma direct conv, cp.async double-buffered ----------------
// CTA: batch b (blockIdx.y), 4 image rows R0..R0+3, all N = NT*8 co. 512 thr = 16 warps.
// K = 9 taps x 64 ci as 4 chunks of 16 ci; taps = shifted smem reads.
// Buffer: sx[ci16][row6][col132] stride 792 (conflict-free);
//         sw blocks per (k,s): NT*64 words, B-frag uint2 index = nt*32 + lane (conflict-free LDS.64).
#define SX_WORDS (16*6*132)

template<int NT, int MODE>   // MODE 0: main conv (*A -> out), MODE 1: se conv1 (relu -> g_hidden)
__global__ void __launch_bounds__(512, 1) conv_mma(float* __restrict__ outp) {
    constexpr int SW_WORDS = 9 * 2 * NT * 64;
    constexpr int BUF_WORDS = SX_WORDS + SW_WORDS;
    extern __shared__ uint32_t sm[];
    const uint32_t smb = smem_u32(sm);
    const int tid = threadIdx.x, wid = tid >> 5, lane = tid & 31;
    const int g = lane >> 2, tig = lane & 3;
    const int b = blockIdx.y, R0 = blockIdx.x * 4;
    const int prow = wid >> 2, colbase = (wid & 3) * 32;

    // hoisted x-staging geometry: thread -> (ci_x, r_x, col quarter)
    const int sr = tid >> 2, q = tid & 3;
    const int ci_x = sr / 6, r_x = sr - ci_x * 6;
    const int gy = R0 - 1 + r_x;
    const bool xactive = sr < 96;
    const bool rowok = xactive && ((unsigned)gy < (unsigned)HH);
    const float* xrowb = g_xc + ((size_t)b * 64) * HW + (size_t)gy * WW - 1;
    const int c0 = q * 33;
    const uint32_t dxrow_off = (uint32_t)(ci_x * 792 + r_x * 132) * 4;

    auto stage = [&](int cc, int bufi) {
        const int ci0 = cc * 16;
        const uint32_t bufb = smb + (uint32_t)bufi * (BUF_WORDS * 4);
        if (xactive) {
            const float* srcrow = xrowb + (size_t)(ci0 + ci_x) * HW;
            const uint32_t drow = bufb + dxrow_off;
            #pragma unroll
            for (int j = 0; j < 33; j++) {
                int c = c0 + j;
                bool ok = rowok && ((unsigned)(c - 1) < (unsigned)WW);
                cp4z(drow + c * 4, srcrow + c, ok);
            }
        }
        // weights: contiguous pre-swizzled block, straight 16B copy
        const float* wsrc = (MODE == 0)
            ? g_wm + ((size_t)(b * 4 + cc)) * SW_WORDS
            : g_ws + (size_t)cc * SW_WORDS;
        constexpr int QUADS = SW_WORDS / 4;
        #pragma unroll
        for (int it = 0; it < (QUADS + 511) / 512; it++) {
            int idx = tid + it * 512;
            if (QUADS % 512 == 0 || idx < QUADS)
                cp16(bufb + (uint32_t)(SX_WORDS + idx * 4) * 4, wsrc + idx * 4);
        }
    };

    float d[2][NT][4];
    #pragma unroll
    for (int mt = 0; mt < 2; mt++)
        #pragma unroll
        for (int nt = 0; nt < NT; nt++)
            #pragma unroll
            for (int r = 0; r < 4; r++) d[mt][nt][r] = 0.f;

    stage(0, 0);
    CP_COMMIT();

    for (int cc = 0; cc < 4; ++cc) {
        if (cc < 3) {
            stage(cc + 1, (cc + 1) & 1);
            CP_COMMIT();
            asm volatile("cp.async.wait_group 1;" ::: "memory");
        } else {
            asm volatile("cp.async.wait_group 0;" ::: "memory");
        }
        __syncthreads();

        const uint32_t* sxp = sm + (cc & 1) * BUF_WORDS;
        const uint32_t* swp = sxp + SX_WORDS;

        #pragma unroll
        for (int k = 0; k < 9; ++k) {
            const int dy = k / 3, dx = k % 3;
            #pragma unroll
            for (int s = 0; s < 2; ++s) {
                uint32_t af[2][4];
                #pragma unroll
                for (int mt = 0; mt < 2; ++mt) {
                    const int colb = colbase + mt * 16 + g + dx;
                    const int base0 = (s * 8 + tig) * 792 + (prow + dy) * 132 + colb;
                    const int base1 = (s * 8 + tig + 4) * 792 + (prow + dy) * 132 + colb;
                    af[mt][0] = sxp[base0];
                    af[mt][1] = sxp[base0 + 8];
                    af[mt][2] = sxp[base1];
                    af[mt][3] = sxp[base1 + 8];
                }
                const uint2* swq = (const uint2*)(swp + (k * 2 + s) * (NT * 64)) + lane;
                #pragma unroll
                for (int nt = 0; nt < NT; ++nt) {
                    uint2 w2 = swq[nt * 32];
                    uint32_t bf[2] = {w2.x, w2.y};
                    mma8(d[0][nt], af[0], bf);
                    mma8(d[1][nt], af[1], bf);
                }
            }
        }
        __syncthreads();
    }

    // epilogue
    const int grow = R0 + prow;
    #pragma unroll
    for (int mt = 0; mt < 2; ++mt) {
        const int col = colbase + mt * 16 + g;
        float av0 = 1.f, av1 = 1.f;
        if (MODE == 0) {
            av0 = g_A[b * HW + grow * WW + col];
            av1 = g_A[b * HW + grow * WW + col + 8];
        }
        #pragma unroll
        for (int nt = 0; nt < NT; ++nt) {
            const int co = nt * 8 + tig * 2;
            if (MODE == 0) {
                float* o0 = outp + ((size_t)(b * 64 + co)) * HW + grow * WW + col;
                float* o1 = o0 + HW;
                o0[0] = d[mt][nt][0] * av0;
                o1[0] = d[mt][nt][1] * av0;
                o0[8] = d[mt][nt][2] * av1;
                o1[8] = d[mt][nt][3] * av1;
            } else {
                float* o0 = g_hidden + ((size_t)(b * 16 + co)) * HW + grow * WW + col;
                float* o1 = o0 + HW;
                o0[0] = fmaxf(d[mt][nt][0], 0.f);
                o1[0] = fmaxf(d[mt][nt][1], 0.f);
                o0[8] = fmaxf(d[mt][nt][2], 0.f);
                o1[8] = fmaxf(d[mt][nt][3], 0.f);
            }
        }
    }
}

// ---------------- SE conv2 (16 -> 1, sigmoid) -> g_A ----------------
__global__ void __launch_bounds__(256) se_conv2(const float* __restrict__ se_w2) {
    __shared__ float sx[16][18][20];
    __shared__ float sw[144];
    int b = blockIdx.z;
    int x0 = blockIdx.x * 16, y0 = blockIdx.y * 16;
    int t = threadIdx.x;
    if (t < 144) sw[t] = se_w2[t];
    for (int idx = t; idx < 16 * 18 * 18; idx += 256) {
        int ci = idx / 324; int rem = idx - ci * 324;
        int r = rem / 18, cx = rem - r * 18;
        int gy = y0 + r - 1, gx = x0 + cx - 1;
        float v = 0.f;
        if ((unsigned)gy < HH && (unsigned)gx < WW)
            v = g_hidden[(b * 16 + ci) * HW + gy * WW + gx];
        sx[ci][r][cx] = v;
    }
    __syncthreads();
    int py = t >> 4, px = t & 15;
    float s = 0.f;
    #pragma unroll
    for (int ci = 0; ci < 16; ci++)
    #pragma unroll
    for (int k = 0; k < 9; k++)
        s += sw[ci * 9 + k] * sx[ci][py + k / 3][px + k % 3];
    g_A[b * HW + (y0 + py) * WW + x0 + px] = 1.f / (1.f + expf(-s));
}

extern "C" void kernel_launch(void* const* d_in, const int* in_sizes, int n_in,
                              void* d_out, int out_size) {
    const float* x      = (const float*)d_in[0];
    const float* weight = (const float*)d_in[1];
    const float* se_w1  = (const float*)d_in[2];
    const float* se_w2  = (const float*)d_in[3];
    const float* fc_w1  = (const float*)d_in[4];
    const float* fc_w2  = (const float*)d_in[5];
    float* out = (float*)d_out;

    const int smem_main = 2 * (SX_WORDS + 9 * 2 * 8 * 64) * 4;
    const int smem_se   = 2 * (SX_WORDS + 9 * 2 * 2 * 64) * 4;
    cudaFuncSetAttribute(conv_mma<8,0>, cudaFuncAttributeMaxDynamicSharedMemorySize, smem_main);
    cudaFuncSetAttribute(conv_mma<2,1>, cudaFuncAttributeMaxDynamicSharedMemorySize, smem_se);

    convert_pool<<<dim3(CB, BB), 256>>>(x);                          // g_xc + g_mean
    attn_fc<<<BB, 576>>>(fc_w1, fc_w2);                              // g_y
    build_w<<<(WM_TOTAL + WS_TOTAL + 255) / 256, 256>>>(weight, se_w1);
    conv_mma<2,1><<<dim3(32, BB), 512, smem_se>>>(nullptr);          // SE conv1 -> g_hidden
    se_conv2<<<dim3(8, 8, BB), 256>>>(se_w2);                        // g_A
    conv_mma<8,0><<<dim3(32, BB), 512, smem_main>>>(out);            // main conv * A -> out
}

// round 7
// speedup vs baseline: 2.4173x; 1.9194x over previous
#include <cuda_runtime.h>
#include <cuda_fp16.h>
#include <cstdint>
#include <math.h>

#define HH 128
#define WW 128
#define HW (HH*WW)
#define CB 64
#define BB 16

// ---------------- scratch (no cudaMalloc allowed) ----------------
__device__ float g_y[BB*576];                    // channel attention [b][ci*9+k]
__device__ uint2 g_wmh[BB*4*9*8*32];             // main weights, B-frag layout [b][cc][k][nt8][lane]
__device__ uint2 g_wsh[4*9*2*32];                // SE weights   [cc][k][nt2][lane]
__device__ float g_hidden[BB*16*HW];             // SE conv1 output
__device__ float g_A[BB*HW];                     // spatial attention
__device__ float g_mean[BB*CB];                  // pooled means
__device__ uint32_t g_xh[(size_t)BB*32*HW];      // fp16 x, half2 ci-pairs: [b][cp32][pos]

__device__ __forceinline__ uint32_t pack_h2(float lo, float hi) {
    __half2 h = __floats2half2_rn(lo, hi);
    return *reinterpret_cast<uint32_t*>(&h);
}
__device__ __forceinline__ void mma16(float* d, const uint32_t* a, uint32_t b0, uint32_t b1) {
    asm volatile(
        "mma.sync.aligned.m16n8k16.row.col.f32.f16.f16.f32 "
        "{%0,%1,%2,%3}, {%4,%5,%6,%7}, {%8,%9}, {%0,%1,%2,%3};\n"
        : "+f"(d[0]), "+f"(d[1]), "+f"(d[2]), "+f"(d[3])
        : "r"(a[0]), "r"(a[1]), "r"(a[2]), "r"(a[3]), "r"(b0), "r"(b1));
}
__device__ __forceinline__ void cp16z(uint32_t dst, const void* src, bool p) {
    asm volatile("cp.async.cg.shared.global [%0], [%1], 16, %2;"
                 :: "r"(dst), "l"(src), "r"(p ? 16u : 0u));
}
__device__ __forceinline__ void cp16(uint32_t dst, const void* src) {
    asm volatile("cp.async.cg.shared.global [%0], [%1], 16;" :: "r"(dst), "l"(src));
}
#define CP_COMMIT() asm volatile("cp.async.commit_group;" ::: "memory")

__device__ __forceinline__ uint32_t smem_u32(const void* p) {
    uint32_t a;
    asm("{ .reg .u64 t; cvta.to.shared.u64 t, %1; cvt.u32.u64 %0, t; }" : "=r"(a) : "l"(p));
    return a;
}

// ---------------- stage 1: fp16 pack (ci-pairs) + global average pool ----------------
__global__ void __launch_bounds__(256) convert_pool(const float* __restrict__ x) {
    int cp = blockIdx.x, b = blockIdx.y, t = threadIdx.x;
    const float4* p0 = (const float4*)(x + ((size_t)(b * 64 + 2 * cp)) * HW);
    const float4* p1 = p0 + HW / 4;
    uint4* o = (uint4*)(g_xh + ((size_t)(b * 32 + cp)) * HW);
    float s0 = 0.f, s1 = 0.f;
    #pragma unroll 4
    for (int i = t; i < HW / 4; i += 256) {
        float4 a = p0[i], c = p1[i];
        s0 += (a.x + a.y) + (a.z + a.w);
        s1 += (c.x + c.y) + (c.z + c.w);
        uint4 w;
        w.x = pack_h2(a.x, c.x);
        w.y = pack_h2(a.y, c.y);
        w.z = pack_h2(a.z, c.z);
        w.w = pack_h2(a.w, c.w);
        o[i] = w;
    }
    #pragma unroll
    for (int off = 16; off; off >>= 1) {
        s0 += __shfl_xor_sync(0xffffffffu, s0, off);
        s1 += __shfl_xor_sync(0xffffffffu, s1, off);
    }
    __shared__ float ws0[8], ws1[8];
    if ((t & 31) == 0) { ws0[t >> 5] = s0; ws1[t >> 5] = s1; }
    __syncthreads();
    if (t == 0) {
        float a0 = 0.f, a1 = 0.f;
        #pragma unroll
        for (int i = 0; i < 8; i++) { a0 += ws0[i]; a1 += ws1[i]; }
        g_mean[b * CB + 2 * cp]     = a0 * (1.f / (float)HW);
        g_mean[b * CB + 2 * cp + 1] = a1 * (1.f / (float)HW);
    }
}

// ---------------- stage 2: FC chain -> y ----------------
__global__ void attn_fc(const float* __restrict__ fc_w1, const float* __restrict__ fc_w2) {
    int b = blockIdx.x, t = threadIdx.x;
    __shared__ float smean[64];
    __shared__ float sh[4];
    if (t < 64) smean[t] = g_mean[b * 64 + t];
    __syncthreads();
    if (t < 4) {
        float s = 0.f;
        #pragma unroll
        for (int c = 0; c < 64; c++) s += smean[c] * fc_w1[t * 64 + c];
        sh[t] = fmaxf(s, 0.f);
    }
    __syncthreads();
    for (int j = t; j < 576; j += blockDim.x) {
        float s = 0.f;
        #pragma unroll
        for (int r = 0; r < 4; r++) s += sh[r] * fc_w2[j * 4 + r];
        g_y[b * 576 + j] = 1.f / (1.f + expf(-s));
    }
}

// ---------------- stage 3: fp16 weights in B-fragment layout ----------------
#define WM_U2 (BB*4*9*8*32)
#define WS_U2 (4*9*2*32)
__global__ void build_w(const float* __restrict__ weight, const float* __restrict__ se_w1) {
    int idx = blockIdx.x * blockDim.x + threadIdx.x;
    if (idx < WM_U2) {
        int lane = idx & 31;
        int nt   = (idx >> 5) & 7;
        int k    = (idx >> 8) % 9;
        int rem  = (idx >> 8) / 9;
        int cc   = rem & 3, b = rem >> 2;
        int g = lane >> 2, tig = lane & 3;
        int co = nt * 8 + g, ci0 = cc * 16;
        float w0 = weight[(co * 64 + ci0 + 2*tig    ) * 9 + k] * g_y[b * 576 + (ci0 + 2*tig    ) * 9 + k];
        float w1 = weight[(co * 64 + ci0 + 2*tig + 1) * 9 + k] * g_y[b * 576 + (ci0 + 2*tig + 1) * 9 + k];
        float w2 = weight[(co * 64 + ci0 + 2*tig + 8) * 9 + k] * g_y[b * 576 + (ci0 + 2*tig + 8) * 9 + k];
        float w3 = weight[(co * 64 + ci0 + 2*tig + 9) * 9 + k] * g_y[b * 576 + (ci0 + 2*tig + 9) * 9 + k];
        g_wmh[idx] = make_uint2(pack_h2(w0, w1), pack_h2(w2, w3));
    } else {
        int j = idx - WM_U2;
        if (j >= WS_U2) return;
        int lane = j & 31;
        int nt   = (j >> 5) & 1;
        int k    = (j >> 6) % 9;
        int cc   = (j >> 6) / 9;
        int g = lane >> 2, tig = lane & 3;
        int co = nt * 8 + g, ci0 = cc * 16;
        float w0 = se_w1[(co * 64 + ci0 + 2*tig    ) * 9 + k];
        float w1 = se_w1[(co * 64 + ci0 + 2*tig + 1) * 9 + k];
        float w2 = se_w1[(co * 64 + ci0 + 2*tig + 8) * 9 + k];
        float w3 = se_w1[(co * 64 + ci0 + 2*tig + 9) * 9 + k];
        g_wsh[j] = make_uint2(pack_h2(w0, w1), pack_h2(w2, w3));
    }
}

// ---------------- fp16 mma direct conv, cp.async double-buffered ----------------
// CTA: batch b, 4 rows R0..R0+3, N = NT*8 co, 512 thr = 16 warps.
// Chunk = 16 ci = 8 half2-pairs; 9 taps; ONE m16n8k16 mma covers the whole chunk per tap.
// sx: [cp8][row6][word136], word = half2(ci even, ci odd) at one position;
//     gx=0 at word 4; halo words 3 & 132 pre-zeroed; cp stride 824 (mod32=24, conflict-free).
// sw: [k][nt][lane] uint2 = B-fragment; LDS.64 at index nt*32+lane (conflict-free).
#define SX_W 6592               // 8 * 824

template<int NT, int MODE, int MINB>   // MODE 0: main conv (*A -> out), 1: se conv1 (relu -> hidden)
__global__ void __launch_bounds__(512, MINB) conv_mma(float* __restrict__ outp) {
    constexpr int SW_W = 9 * NT * 64;
    constexpr int BUF_W = SX_W + SW_W;
    extern __shared__ uint32_t sm[];
    const uint32_t smb = smem_u32(sm);
    const int tid = threadIdx.x, wid = tid >> 5, lane = tid & 31;
    const int g = lane >> 2, tig = lane & 3;
    const int b = blockIdx.y, R0 = blockIdx.x * 4;
    const int prow = wid >> 2, colbase = (wid & 3) * 32;

    // x-staging geometry: 48 (cp,row) slots x 8 col-eighths
    const int sr = tid >> 3, q = tid & 7;
    const int cp_x = sr / 6, r_x = sr - cp_x * 6;
    const int gy = R0 - 1 + r_x;
    const bool xact = sr < 48;
    const bool rowok = xact && ((unsigned)gy < (unsigned)HH);
    const uint32_t* xrow = g_xh + ((size_t)(b * 32 + cp_x)) * HW + (ptrdiff_t)gy * WW + q * 16;
    const uint32_t dxoff = (uint32_t)(cp_x * 824 + r_x * 136 + 4 + q * 16) * 4;

    // one-time halo zero (words 3 and 132 of every (cp,row), both buffers)
    if (xact && q == 0) {
        #pragma unroll
        for (int bi = 0; bi < 2; bi++) {
            sm[bi * BUF_W + cp_x * 824 + r_x * 136 + 3]   = 0;
            sm[bi * BUF_W + cp_x * 824 + r_x * 136 + 132] = 0;
        }
    }

    auto stage = [&](int cc, int bufi) {
        const uint32_t bufb = smb + (uint32_t)bufi * (BUF_W * 4);
        if (xact) {
            const uint32_t* src = xrow + (size_t)(cc * 8) * HW;
            const uint32_t dst = bufb + dxoff;
            #pragma unroll
            for (int j = 0; j < 4; j++)
                cp16z(dst + j * 16, src + j * 4, rowok);
        }
        // weights: contiguous pre-swizzled block
        const uint4* wsrc = (const uint4*)((MODE == 0)
            ? g_wmh + (size_t)(b * 4 + cc) * (SW_W / 2)
            : g_wsh + (size_t)cc * (SW_W / 2));
        constexpr int QUADS = SW_W / 4;
        #pragma unroll
        for (int it = 0; it < (QUADS + 511) / 512; it++) {
            int idx = tid + it * 512;
            if (QUADS % 512 == 0 || idx < QUADS)
                cp16(bufb + (uint32_t)(SX_W + idx * 4) * 4, wsrc + idx);
        }
    };

    float d[2][NT][4];
    #pragma unroll
    for (int mt = 0; mt < 2; mt++)
        #pragma unroll
        for (int nt = 0; nt < NT; nt++)
            #pragma unroll
            for (int r = 0; r < 4; r++) d[mt][nt][r] = 0.f;

    stage(0, 0);
    CP_COMMIT();

    for (int cc = 0; cc < 4; ++cc) {
        if (cc < 3) {
            stage(cc + 1, (cc + 1) & 1);
            CP_COMMIT();
            asm volatile("cp.async.wait_group 1;" ::: "memory");
        } else {
            asm volatile("cp.async.wait_group 0;" ::: "memory");
        }
        __syncthreads();

        const uint32_t* sxp = sm + (cc & 1) * BUF_W;
        const uint32_t* swp = sxp + SX_W;

        #pragma unroll
        for (int k = 0; k < 9; ++k) {
            const int dy = k / 3, dx = k % 3;
            uint32_t af[2][4];
            #pragma unroll
            for (int mt = 0; mt < 2; ++mt) {
                const int colb = colbase + mt * 16 + g + dx + 3;
                const int b0 = tig * 824 + (prow + dy) * 136 + colb;
                af[mt][0] = sxp[b0];
                af[mt][1] = sxp[b0 + 8];
                af[mt][2] = sxp[b0 + 4 * 824];
                af[mt][3] = sxp[b0 + 4 * 824 + 8];
            }
            const uint2* swq = (const uint2*)(swp + k * (NT * 64)) + lane;
            #pragma unroll
            for (int nt = 0; nt < NT; ++nt) {
                uint2 w2 = swq[nt * 32];
                mma16(d[0][nt], af[0], w2.x, w2.y);
                mma16(d[1][nt], af[1], w2.x, w2.y);
            }
        }
        __syncthreads();
    }

    // epilogue
    const int grow = R0 + prow;
    #pragma unroll
    for (int mt = 0; mt < 2; ++mt) {
        const int col = colbase + mt * 16 + g;
        float av0 = 1.f, av1 = 1.f;
        if (MODE == 0) {
            av0 = g_A[b * HW + grow * WW + col];
            av1 = g_A[b * HW + grow * WW + col + 8];
        }
        #pragma unroll
        for (int nt = 0; nt < NT; ++nt) {
            const int co = nt * 8 + tig * 2;
            if (MODE == 0) {
                float* o0 = outp + ((size_t)(b * 64 + co)) * HW + grow * WW + col;
                float* o1 = o0 + HW;
                o0[0] = d[mt][nt][0] * av0;
                o1[0] = d[mt][nt][1] * av0;
                o0[8] = d[mt][nt][2] * av1;
                o1[8] = d[mt][nt][3] * av1;
            } else {
                float* o0 = g_hidden + ((size_t)(b * 16 + co)) * HW + grow * WW + col;
                float* o1 = o0 + HW;
                o0[0] = fmaxf(d[mt][nt][0], 0.f);
                o1[0] = fmaxf(d[mt][nt][1], 0.f);
                o0[8] = fmaxf(d[mt][nt][2], 0.f);
                o1[8] = fmaxf(d[mt][nt][3], 0.f);
            }
        }
    }
}

// ---------------- SE conv2 (16 -> 1, sigmoid) -> g_A ----------------
__global__ void __launch_bounds__(256) se_conv2(const float* __restrict__ se_w2) {
    __shared__ float sx[16][18][20];
    __shared__ float sw[144];
    int b = blockIdx.z;
    int x0 = blockIdx.x * 16, y0 = blockIdx.y * 16;
    int t = threadIdx.x;
    if (t < 144) sw[t] = se_w2[t];
    for (int idx = t; idx < 16 * 18 * 18; idx += 256) {
        int ci = idx / 324; int rem = idx - ci * 324;
        int r = rem / 18, cx = rem - r * 18;
        int gy = y0 + r - 1, gx = x0 + cx - 1;
        float v = 0.f;
        if ((unsigned)gy < HH && (unsigned)gx < WW)
            v = g_hidden[(b * 16 + ci) * HW + gy * WW + gx];
        sx[ci][r][cx] = v;
    }
    __syncthreads();
    int py = t >> 4, px = t & 15;
    float s = 0.f;
    #pragma unroll
    for (int ci = 0; ci < 16; ci++)
    #pragma unroll
    for (int k = 0; k < 9; k++)
        s += sw[ci * 9 + k] * sx[ci][py + k / 3][px + k % 3];
    g_A[b * HW + (y0 + py) * WW + x0 + px] = 1.f / (1.f + expf(-s));
}

extern "C" void kernel_launch(void* const* d_in, const int* in_sizes, int n_in,
                              void* d_out, int out_size) {
    const float* x      = (const float*)d_in[0];
    const float* weight = (const float*)d_in[1];
    const float* se_w1  = (const float*)d_in[2];
    const float* se_w2  = (const float*)d_in[3];
    const float* fc_w1  = (const float*)d_in[4];
    const float* fc_w2  = (const float*)d_in[5];
    float* out = (float*)d_out;

    const int smem_main = 2 * (SX_W + 9 * 8 * 64) * 4;   // 89.6 KB
    const int smem_se   = 2 * (SX_W + 9 * 2 * 64) * 4;   // 62.0 KB
    cudaFuncSetAttribute((const void*)conv_mma<8,0,1>,
                         cudaFuncAttributeMaxDynamicSharedMemorySize, smem_main);
    cudaFuncSetAttribute((const void*)conv_mma<2,1,2>,
                         cudaFuncAttributeMaxDynamicSharedMemorySize, smem_se);

    convert_pool<<<dim3(32, BB), 256>>>(x);                          // g_xh + g_mean
    attn_fc<<<BB, 576>>>(fc_w1, fc_w2);                              // g_y
    build_w<<<(WM_U2 + WS_U2 + 255) / 256, 256>>>(weight, se_w1);    // g_wmh + g_wsh
    conv_mma<2,1,2><<<dim3(32, BB), 512, smem_se>>>(nullptr);        // SE conv1 -> g_hidden
    se_conv2<<<dim3(8, 8, BB), 256>>>(se_w2);                        // g_A
    conv_mma<8,0,1><<<dim3(32, BB), 512, smem_main>>>(out);          // main conv * A -> out
}

// round 8
// speedup vs baseline: 2.4823x; 1.0269x over previous
#include <cuda_runtime.h>
#include <cuda_fp16.h>
#include <cstdint>
#include <math.h>

#define HH 128
#define WW 128
#define HW (HH*WW)
#define CB 64
#define BB 16

// ---------------- scratch (no cudaMalloc allowed) ----------------
__device__ float g_y[BB*576];                    // channel attention [b][ci*9+k]
__device__ uint2 g_wmh[BB*2*4*9*4*32];           // main weights [b][z][cc][k][nt4][lane]
__device__ uint2 g_wsh[4*9*2*32];                // SE weights   [cc][k][nt2][lane]
__device__ float g_hidden[BB*16*HW];             // SE conv1 output
__device__ float g_A[BB*HW];                     // spatial attention
__device__ float g_mean[BB*CB];                  // pooled means
__device__ uint32_t g_xh[(size_t)BB*32*HW];      // fp16 x, half2 ci-pairs: [b][cp32][pos]

__device__ __forceinline__ uint32_t pack_h2(float lo, float hi) {
    __half2 h = __floats2half2_rn(lo, hi);
    return *reinterpret_cast<uint32_t*>(&h);
}
__device__ __forceinline__ void mma16(float* d, const uint32_t* a, uint32_t b0, uint32_t b1) {
    asm volatile(
        "mma.sync.aligned.m16n8k16.row.col.f32.f16.f16.f32 "
        "{%0,%1,%2,%3}, {%4,%5,%6,%7}, {%8,%9}, {%0,%1,%2,%3};\n"
        : "+f"(d[0]), "+f"(d[1]), "+f"(d[2]), "+f"(d[3])
        : "r"(a[0]), "r"(a[1]), "r"(a[2]), "r"(a[3]), "r"(b0), "r"(b1));
}
__device__ __forceinline__ void cp16z(uint32_t dst, const void* src, bool p) {
    asm volatile("cp.async.cg.shared.global [%0], [%1], 16, %2;"
                 :: "r"(dst), "l"(src), "r"(p ? 16u : 0u));
}
__device__ __forceinline__ void cp16(uint32_t dst, const void* src) {
    asm volatile("cp.async.cg.shared.global [%0], [%1], 16;" :: "r"(dst), "l"(src));
}
#define CP_COMMIT() asm volatile("cp.async.commit_group;" ::: "memory")

__device__ __forceinline__ uint32_t smem_u32(const void* p) {
    uint32_t a;
    asm("{ .reg .u64 t; cvta.to.shared.u64 t, %1; cvt.u32.u64 %0, t; }" : "=r"(a) : "l"(p));
    return a;
}

// ---------------- stage 1: fp16 pack (ci-pairs) + global average pool ----------------
__global__ void __launch_bounds__(256) convert_pool(const float* __restrict__ x) {
    int cp = blockIdx.x, b = blockIdx.y, t = threadIdx.x;
    const float4* p0 = (const float4*)(x + ((size_t)(b * 64 + 2 * cp)) * HW);
    const float4* p1 = p0 + HW / 4;
    uint4* o = (uint4*)(g_xh + ((size_t)(b * 32 + cp)) * HW);
    float s0 = 0.f, s1 = 0.f;
    #pragma unroll 4
    for (int i = t; i < HW / 4; i += 256) {
        float4 a = p0[i], c = p1[i];
        s0 += (a.x + a.y) + (a.z + a.w);
        s1 += (c.x + c.y) + (c.z + c.w);
        uint4 w;
        w.x = pack_h2(a.x, c.x);
        w.y = pack_h2(a.y, c.y);
        w.z = pack_h2(a.z, c.z);
        w.w = pack_h2(a.w, c.w);
        o[i] = w;
    }
    #pragma unroll
    for (int off = 16; off; off >>= 1) {
        s0 += __shfl_xor_sync(0xffffffffu, s0, off);
        s1 += __shfl_xor_sync(0xffffffffu, s1, off);
    }
    __shared__ float ws0[8], ws1[8];
    if ((t & 31) == 0) { ws0[t >> 5] = s0; ws1[t >> 5] = s1; }
    __syncthreads();
    if (t == 0) {
        float a0 = 0.f, a1 = 0.f;
        #pragma unroll
        for (int i = 0; i < 8; i++) { a0 += ws0[i]; a1 += ws1[i]; }
        g_mean[b * CB + 2 * cp]     = a0 * (1.f / (float)HW);
        g_mean[b * CB + 2 * cp + 1] = a1 * (1.f / (float)HW);
    }
}

// ---------------- stage 2: FC chain -> y ----------------
__global__ void attn_fc(const float* __restrict__ fc_w1, const float* __restrict__ fc_w2) {
    int b = blockIdx.x, t = threadIdx.x;
    __shared__ float smean[64];
    __shared__ float sh[4];
    if (t < 64) smean[t] = g_mean[b * 64 + t];
    __syncthreads();
    if (t < 4) {
        float s = 0.f;
        #pragma unroll
        for (int c = 0; c < 64; c++) s += smean[c] * fc_w1[t * 64 + c];
        sh[t] = fmaxf(s, 0.f);
    }
    __syncthreads();
    for (int j = t; j < 576; j += blockDim.x) {
        float s = 0.f;
        #pragma unroll
        for (int r = 0; r < 4; r++) s += sh[r] * fc_w2[j * 4 + r];
        g_y[b * 576 + j] = 1.f / (1.f + expf(-s));
    }
}

// ---------------- stage 3: fp16 weights in B-fragment layout ----------------
#define WM_U2 (BB*2*4*9*4*32)
#define WS_U2 (4*9*2*32)
__global__ void build_w(const float* __restrict__ weight, const float* __restrict__ se_w1) {
    int idx = blockIdx.x * blockDim.x + threadIdx.x;
    if (idx < WM_U2) {
        int lane = idx & 31;
        int nt   = (idx >> 5) & 3;
        int k    = (idx >> 7) % 9;
        int rem  = (idx >> 7) / 9;
        int cc   = rem & 3;
        int z    = (rem >> 2) & 1;
        int b    = rem >> 3;
        int g = lane >> 2, tig = lane & 3;
        int co = z * 32 + nt * 8 + g, ci0 = cc * 16;
        float w0 = weight[(co * 64 + ci0 + 2*tig    ) * 9 + k] * g_y[b * 576 + (ci0 + 2*tig    ) * 9 + k];
        float w1 = weight[(co * 64 + ci0 + 2*tig + 1) * 9 + k] * g_y[b * 576 + (ci0 + 2*tig + 1) * 9 + k];
        float w2 = weight[(co * 64 + ci0 + 2*tig + 8) * 9 + k] * g_y[b * 576 + (ci0 + 2*tig + 8) * 9 + k];
        float w3 = weight[(co * 64 + ci0 + 2*tig + 9) * 9 + k] * g_y[b * 576 + (ci0 + 2*tig + 9) * 9 + k];
        g_wmh[idx] = make_uint2(pack_h2(w0, w1), pack_h2(w2, w3));
    } else {
        int j = idx - WM_U2;
        if (j >= WS_U2) return;
        int lane = j & 31;
        int nt   = (j >> 5) & 1;
        int k    = (j >> 6) % 9;
        int cc   = (j >> 6) / 9;
        int g = lane >> 2, tig = lane & 3;
        int co = nt * 8 + g, ci0 = cc * 16;
        float w0 = se_w1[(co * 64 + ci0 + 2*tig    ) * 9 + k];
        float w1 = se_w1[(co * 64 + ci0 + 2*tig + 1) * 9 + k];
        float w2 = se_w1[(co * 64 + ci0 + 2*tig + 8) * 9 + k];
        float w3 = se_w1[(co * 64 + ci0 + 2*tig + 9) * 9 + k];
        g_wsh[j] = make_uint2(pack_h2(w0, w1), pack_h2(w2, w3));
    }
}

// ---------------- fp16 mma direct conv, cp.async double-buffered, 2 CTAs/SM ----------------
// CTA: batch b (blockIdx.y), 4 rows R0..R0+3 (blockIdx.x), co half z (blockIdx.z, MODE 0 only).
// N = NT*8 co per CTA. 512 thr = 16 warps. Chunk = 16 ci = 8 half2-pairs; 9 taps;
// one m16n8k16 mma covers the whole chunk per tap.
// sx: [cp8][row6][word136], halo words 3 & 132 pre-zeroed; cp stride 824 (conflict-free).
// sw: [k][nt][lane] uint2 B-fragment; LDS.64 at index nt*32+lane (conflict-free).
#define SX_W 6592               // 8 * 824

template<int NT, int MODE>   // MODE 0: main conv half (*A -> out), 1: se conv1 (relu -> hidden)
__global__ void __launch_bounds__(512, 2) conv_mma(float* __restrict__ outp) {
    constexpr int SW_W = 9 * NT * 64;
    constexpr int BUF_W = SX_W + SW_W;
    extern __shared__ uint32_t sm[];
    const uint32_t smb = smem_u32(sm);
    const int tid = threadIdx.x, wid = tid >> 5, lane = tid & 31;
    const int g = lane >> 2, tig = lane & 3;
    const int b = blockIdx.y, R0 = blockIdx.x * 4;
    const int zz = (MODE == 0) ? blockIdx.z : 0;
    const int co_base = zz * 32;
    const int prow = wid >> 2, colbase = (wid & 3) * 32;

    // x-staging geometry: 48 (cp,row) slots x 8 col-eighths
    const int sr = tid >> 3, q = tid & 7;
    const int cp_x = sr / 6, r_x = sr - cp_x * 6;
    const int gy = R0 - 1 + r_x;
    const bool xact = sr < 48;
    const bool rowok = xact && ((unsigned)gy < (unsigned)HH);
    const uint32_t* xrow = g_xh + ((size_t)(b * 32 + cp_x)) * HW + (ptrdiff_t)gy * WW + q * 16;
    const uint32_t dxoff = (uint32_t)(cp_x * 824 + r_x * 136 + 4 + q * 16) * 4;

    // one-time halo zero (words 3 and 132 of every (cp,row), both buffers)
    if (xact && q == 0) {
        #pragma unroll
        for (int bi = 0; bi < 2; bi++) {
            sm[bi * BUF_W + cp_x * 824 + r_x * 136 + 3]   = 0;
            sm[bi * BUF_W + cp_x * 824 + r_x * 136 + 132] = 0;
        }
    }

    auto stage = [&](int cc, int bufi) {
        const uint32_t bufb = smb + (uint32_t)bufi * (BUF_W * 4);
        if (xact) {
            const uint32_t* src = xrow + (size_t)(cc * 8) * HW;
            const uint32_t dst = bufb + dxoff;
            #pragma unroll
            for (int j = 0; j < 4; j++)
                cp16z(dst + j * 16, src + j * 4, rowok);
        }
        // weights: contiguous pre-swizzled block
        const uint4* wsrc = (const uint4*)((MODE == 0)
            ? g_wmh + (size_t)(((b * 2 + zz) * 4 + cc)) * (SW_W / 2)
            : g_wsh + (size_t)cc * (SW_W / 2));
        constexpr int QUADS = SW_W / 4;
        #pragma unroll
        for (int it = 0; it < (QUADS + 511) / 512; it++) {
            int idx = tid + it * 512;
            if (QUADS % 512 == 0 || idx < QUADS)
                cp16(bufb + (uint32_t)(SX_W + idx * 4) * 4, wsrc + idx);
        }
    };

    float d[2][NT][4];
    #pragma unroll
    for (int mt = 0; mt < 2; mt++)
        #pragma unroll
        for (int nt = 0; nt < NT; nt++)
            #pragma unroll
            for (int r = 0; r < 4; r++) d[mt][nt][r] = 0.f;

    stage(0, 0);
    CP_COMMIT();

    for (int cc = 0; cc < 4; ++cc) {
        if (cc < 3) {
            stage(cc + 1, (cc + 1) & 1);
            CP_COMMIT();
            asm volatile("cp.async.wait_group 1;" ::: "memory");
        } else {
            asm volatile("cp.async.wait_group 0;" ::: "memory");
        }
        __syncthreads();

        const uint32_t* sxp = sm + (cc & 1) * BUF_W;
        const uint32_t* swp = sxp + SX_W;

        #pragma unroll
        for (int k = 0; k < 9; ++k) {
            const int dy = k / 3, dx = k % 3;
            uint32_t af[2][4];
            #pragma unroll
            for (int mt = 0; mt < 2; ++mt) {
                const int colb = colbase + mt * 16 + g + dx + 3;
                const int b0 = tig * 824 + (prow + dy) * 136 + colb;
                af[mt][0] = sxp[b0];
                af[mt][1] = sxp[b0 + 8];
                af[mt][2] = sxp[b0 + 4 * 824];
                af[mt][3] = sxp[b0 + 4 * 824 + 8];
            }
            const uint2* swq = (const uint2*)(swp + k * (NT * 64)) + lane;
            #pragma unroll
            for (int nt = 0; nt < NT; ++nt) {
                uint2 w2 = swq[nt * 32];
                mma16(d[0][nt], af[0], w2.x, w2.y);
                mma16(d[1][nt], af[1], w2.x, w2.y);
            }
        }
        __syncthreads();
    }

    // epilogue
    const int grow = R0 + prow;
    #pragma unroll
    for (int mt = 0; mt < 2; ++mt) {
        const int col = colbase + mt * 16 + g;
        float av0 = 1.f, av1 = 1.f;
        if (MODE == 0) {
            av0 = g_A[b * HW + grow * WW + col];
            av1 = g_A[b * HW + grow * WW + col + 8];
        }
        #pragma unroll
        for (int nt = 0; nt < NT; ++nt) {
            const int co = co_base + nt * 8 + tig * 2;
            if (MODE == 0) {
                float* o0 = outp + ((size_t)(b * 64 + co)) * HW + grow * WW + col;
                float* o1 = o0 + HW;
                o0[0] = d[mt][nt][0] * av0;
                o1[0] = d[mt][nt][1] * av0;
                o0[8] = d[mt][nt][2] * av1;
                o1[8] = d[mt][nt][3] * av1;
            } else {
                float* o0 = g_hidden + ((size_t)(b * 16 + co)) * HW + grow * WW + col;
                float* o1 = o0 + HW;
                o0[0] = fmaxf(d[mt][nt][0], 0.f);
                o1[0] = fmaxf(d[mt][nt][1], 0.f);
                o0[8] = fmaxf(d[mt][nt][2], 0.f);
                o1[8] = fmaxf(d[mt][nt][3], 0.f);
            }
        }
    }
}

// ---------------- SE conv2 (16 -> 1, sigmoid) -> g_A ----------------
__global__ void __launch_bounds__(256) se_conv2(const float* __restrict__ se_w2) {
    __shared__ float sx[16][18][20];
    __shared__ float sw[144];
    int b = blockIdx.z;
    int x0 = blockIdx.x * 16, y0 = blockIdx.y * 16;
    int t = threadIdx.x;
    if (t < 144) sw[t] = se_w2[t];
    for (int idx = t; idx < 16 * 18 * 18; idx += 256) {
        int ci = idx / 324; int rem = idx - ci * 324;
        int r = rem / 18, cx = rem - r * 18;
        int gy = y0 + r - 1, gx = x0 + cx - 1;
        float v = 0.f;
        if ((unsigned)gy < HH && (unsigned)gx < WW)
            v = g_hidden[(b * 16 + ci) * HW + gy * WW + gx];
        sx[ci][r][cx] = v;
    }
    __syncthreads();
    int py = t >> 4, px = t & 15;
    float s = 0.f;
    #pragma unroll
    for (int ci = 0; ci < 16; ci++)
    #pragma unroll
    for (int k = 0; k < 9; k++)
        s += sw[ci * 9 + k] * sx[ci][py + k / 3][px + k % 3];
    g_A[b * HW + (y0 + py) * WW + x0 + px] = 1.f / (1.f + expf(-s));
}

extern "C" void kernel_launch(void* const* d_in, const int* in_sizes, int n_in,
                              void* d_out, int out_size) {
    const float* x      = (const float*)d_in[0];
    const float* weight = (const float*)d_in[1];
    const float* se_w1  = (const float*)d_in[2];
    const float* se_w2  = (const float*)d_in[3];
    const float* fc_w1  = (const float*)d_in[4];
    const float* fc_w2  = (const float*)d_in[5];
    float* out = (float*)d_out;

    const int smem_main = 2 * (SX_W + 9 * 4 * 64) * 4;   // 71.2 KB -> 2 CTAs/SM
    const int smem_se   = 2 * (SX_W + 9 * 2 * 64) * 4;   // 62.0 KB -> 2 CTAs/SM
    cudaFuncSetAttribute((const void*)conv_mma<4,0>,
                         cudaFuncAttributeMaxDynamicSharedMemorySize, smem_main);
    cudaFuncSetAttribute((const void*)conv_mma<2,1>,
                         cudaFuncAttributeMaxDynamicSharedMemorySize, smem_se);

    convert_pool<<<dim3(32, BB), 256>>>(x);                          // g_xh + g_mean
    attn_fc<<<BB, 576>>>(fc_w1, fc_w2);                              // g_y
    build_w<<<(WM_U2 + WS_U2 + 255) / 256, 256>>>(weight, se_w1);    // g_wmh + g_wsh
    conv_mma<2,1><<<dim3(32, BB), 512, smem_se>>>(nullptr);          // SE conv1 -> g_hidden
    se_conv2<<<dim3(8, 8, BB), 256>>>(se_w2);                        // g_A
    conv_mma<4,0><<<dim3(32, BB, 2), 512, smem_main>>>(out);         // main conv * A -> out
}